// round 4
// baseline (speedup 1.0000x reference)
#include <cuda_runtime.h>
#include <math.h>

#define NN    4096
#define DD    64
#define T     1024
#define FULL  0xFFFFFFFFu

// Cross-call state (zero-initialized; reset by last block each launch).
__device__ double       g_acc;
__device__ unsigned int g_done;

__device__ __forceinline__ void lse_combine(float& m1, float& s1, float m2, float s2) {
    if (m2 > m1) { s1 = s1 * __expf(m1 - m2) + s2; m1 = m2; }
    else         { s1 = s1 + s2 * __expf(m2 - m1); }
}

__device__ __forceinline__ void lse_push(float& m, float& sv, float x) {
    if (x > m) { sv = sv * __expf(m - x) + 1.0f; m = x; }
    else       { sv += __expf(x - m); }
}

__device__ __forceinline__ float dot4(float4 a, float4 b) {
    return a.x * b.x + a.y * b.y + a.z * b.z + a.w * b.w;
}

__global__ __launch_bounds__(T, 2) void fused_kernel(const float* __restrict__ X,
                                                     const float* __restrict__ W,
                                                     const float* __restrict__ bias,
                                                     const int* __restrict__ rankings,
                                                     float* __restrict__ out) {
    __shared__ float s_sc[NN];
    __shared__ float s_wm[32];
    __shared__ float s_ws[32];
    __shared__ float s_red[32];

    const int b    = blockIdx.x;
    const int tid  = threadIdx.x;
    const int grp  = tid >> 4;      // score within 64-wide stripe
    const int gl   = tid & 15;      // lane within 16-lane dot group
    const int lane = tid & 31;
    const int wrp  = tid >> 5;

    // Issue rankings load early (independent of X stream).
    const int4 r = __ldcs(&reinterpret_cast<const int4*>(rankings + (size_t)b * NN)[tid]);

    // -------- Phase 1: scores[b,:] = X[b] @ W + b0 --------------------------
    const float4  wv = reinterpret_cast<const float4*>(W)[gl];
    const float   b0 = bias[0];
    const float4* Xv = reinterpret_cast<const float4*>(X + (size_t)b * NN * DD);
    // float4 index for (score s, chunk gl) = s*16 + gl = k*1024 + tid

    #pragma unroll 4
    for (int k0 = 0; k0 < NN / 64; k0 += 2) {
        const float4 xa = __ldcs(Xv + ((size_t)k0 * 1024 + tid));
        const float4 xb = __ldcs(Xv + ((size_t)k0 * 1024 + 1024 + tid));
        float pa = dot4(xa, wv);
        float pb = dot4(xb, wv);
        pa += __shfl_xor_sync(FULL, pa, 8);
        pb += __shfl_xor_sync(FULL, pb, 8);
        pa += __shfl_xor_sync(FULL, pa, 4);
        pb += __shfl_xor_sync(FULL, pb, 4);
        pa += __shfl_xor_sync(FULL, pa, 2);
        pb += __shfl_xor_sync(FULL, pb, 2);
        pa += __shfl_xor_sync(FULL, pa, 1);
        pb += __shfl_xor_sync(FULL, pb, 1);
        if (gl == 0) {
            s_sc[k0 * 64 + grp]       = pa + b0;
            s_sc[k0 * 64 + 64 + grp]  = pb + b0;
        }
    }
    __syncthreads();

    // -------- Phase 2: gather 4 elements by ranking -------------------------
    const float x0 = s_sc[r.x & (NN - 1)];
    const float x1 = s_sc[r.y & (NN - 1)];
    const float x2 = s_sc[r.z & (NN - 1)];
    const float x3 = s_sc[r.w & (NN - 1)];

    // -------- Phase 3: local suffix aggregate (x3 -> x0) --------------------
    float m = x3, sv = 1.0f;
    lse_push(m, sv, x2);
    lse_push(m, sv, x1);
    lse_push(m, sv, x0);

    // -------- Phase 4: warp inclusive suffix scan ----------------------------
    float mm = m, ss = sv;
    #pragma unroll
    for (int d = 1; d < 32; d <<= 1) {
        const float mo = __shfl_down_sync(FULL, mm, d);
        const float so = __shfl_down_sync(FULL, ss, d);
        if (lane + d < 32) lse_combine(mm, ss, mo, so);
    }
    if (lane == 0) { s_wm[wrp] = mm; s_ws[wrp] = ss; }
    __syncthreads();

    if (wrp == 0) {
        float am = s_wm[lane], as = s_ws[lane];
        #pragma unroll
        for (int d = 1; d < 32; d <<= 1) {
            const float mo = __shfl_down_sync(FULL, am, d);
            const float so = __shfl_down_sync(FULL, as, d);
            if (lane + d < 32) lse_combine(am, as, mo, so);
        }
        s_wm[lane] = am; s_ws[lane] = as;
    }
    __syncthreads();

    // -------- Phase 5: exclusive suffix carry --------------------------------
    const float em_raw = __shfl_down_sync(FULL, mm, 1);
    const float es_raw = __shfl_down_sync(FULL, ss, 1);
    const float em = (lane < 31) ? em_raw : -INFINITY;
    const float es = (lane < 31) ? es_raw : 0.0f;
    const float cm = (wrp < 31) ? s_wm[wrp + 1] : -INFINITY;
    const float cs = (wrp < 31) ? s_ws[wrp + 1] : 0.0f;

    float Mc, Sc;
    if (cm > em)             { Sc = es * __expf(em - cm) + cs; Mc = cm; }
    else if (em > -INFINITY) { Sc = es + cs * __expf(cm - em); Mc = em; }
    else                     { Mc = -INFINITY; Sc = 0.0f; }

    // -------- Phase 6: replay chunk, emit denom per element ------------------
    float rm = -INFINITY, rs = 0.0f, acc = 0.0f;
    const float xs[4] = {x3, x2, x1, x0};
    #pragma unroll
    for (int j = 0; j < 4; j++) {
        const float x = xs[j];
        lse_push(rm, rs, x);
        float denom;
        if (rm >= Mc) denom = rm + __logf(rs + Sc * __expf(Mc - rm));
        else          denom = Mc + __logf(Sc + rs * __expf(rm - Mc));
        acc += x - denom;
    }

    // -------- Phase 7: block reduce + completion-counter finalize ------------
    #pragma unroll
    for (int o = 16; o; o >>= 1) acc += __shfl_xor_sync(FULL, acc, o);
    if (lane == 0) s_red[wrp] = acc;
    __syncthreads();
    if (tid == 0) {
        float t = 0.0f;
        #pragma unroll
        for (int w = 0; w < 32; w++) t += s_red[w];
        atomicAdd(&g_acc, (double)t);
        __threadfence();
        const unsigned int ticket = atomicAdd(&g_done, 1u);
        if (ticket == gridDim.x - 1) {
            out[0] = (float)(-g_acc / (double)gridDim.x);
            g_acc  = 0.0;      // reset for next graph replay
            g_done = 0u;
            __threadfence();
        }
    }
}

extern "C" void kernel_launch(void* const* d_in, const int* in_sizes, int n_in,
                              void* d_out, int out_size) {
    const float* X        = (const float*)d_in[0];
    const float* W        = (const float*)d_in[1];
    const float* bias     = (const float*)d_in[2];
    const int*   rankings = (const int*)d_in[3];
    float* out = (float*)d_out;

    const int BN = in_sizes[3];   // B * N
    const int B  = BN / NN;       // N fixed at 4096

    fused_kernel<<<B, T>>>(X, W, bias, rankings, out);
}

// round 5
// speedup vs baseline: 1.0287x; 1.0287x over previous
#include <cuda_runtime.h>
#include <math.h>

#define NN    4096
#define DD    64
#define T     1024
#define FULL  0xFFFFFFFFu

// Cross-call state (zero-initialized; reset by last block each launch).
__device__ double       g_acc;
__device__ unsigned int g_done;

__device__ __forceinline__ float dot4(float4 a, float4 b) {
    return a.x * b.x + a.y * b.y + a.z * b.z + a.w * b.w;
}

__global__ __launch_bounds__(T, 2) void fused_kernel(const float* __restrict__ X,
                                                     const float* __restrict__ W,
                                                     const float* __restrict__ bias,
                                                     const int* __restrict__ rankings,
                                                     float* __restrict__ out) {
    __shared__ float s_sc[NN];     // scores for this row
    __shared__ float s_ws[32];     // per-warp suffix sums / max staging
    __shared__ float s_red[32];
    __shared__ float s_M;          // row max broadcast

    const int b    = blockIdx.x;
    const int tid  = threadIdx.x;
    const int grp  = tid >> 4;      // score within 64-wide stripe
    const int gl   = tid & 15;      // lane within 16-lane dot group
    const int lane = tid & 31;
    const int wrp  = tid >> 5;

    // Rankings load issued early (independent of X stream); 4 regs.
    const int4 r = reinterpret_cast<const int4*>(rankings + (size_t)b * NN)[tid];

    // -------- Phase 1: scores[b,:] = X[b] @ W + b0 --------------------------
    const float4  wv = reinterpret_cast<const float4*>(W)[gl];
    const float   b0 = bias[0];
    const float4* Xv = reinterpret_cast<const float4*>(X + (size_t)b * NN * DD);

    #pragma unroll 4
    for (int k0 = 0; k0 < NN / 64; k0 += 2) {
        const float4 xa = Xv[(size_t)k0 * 1024 + tid];
        const float4 xb = Xv[(size_t)k0 * 1024 + 1024 + tid];
        float pa = dot4(xa, wv);
        float pb = dot4(xb, wv);
        pa += __shfl_xor_sync(FULL, pa, 8);
        pb += __shfl_xor_sync(FULL, pb, 8);
        pa += __shfl_xor_sync(FULL, pa, 4);
        pb += __shfl_xor_sync(FULL, pb, 4);
        pa += __shfl_xor_sync(FULL, pa, 2);
        pb += __shfl_xor_sync(FULL, pb, 2);
        pa += __shfl_xor_sync(FULL, pa, 1);
        pb += __shfl_xor_sync(FULL, pb, 1);
        if (gl == 0) {
            s_sc[k0 * 64 + grp]      = pa + b0;
            s_sc[k0 * 64 + 64 + grp] = pb + b0;
        }
    }
    __syncthreads();

    // -------- Phase 2: gather 4 elements (positions 4*tid .. 4*tid+3) -------
    const float x0 = s_sc[r.x & (NN - 1)];
    const float x1 = s_sc[r.y & (NN - 1)];
    const float x2 = s_sc[r.z & (NN - 1)];
    const float x3 = s_sc[r.w & (NN - 1)];

    // -------- Phase 3: block max over gathered values ------------------------
    float mx = fmaxf(fmaxf(x0, x1), fmaxf(x2, x3));
    #pragma unroll
    for (int o = 16; o; o >>= 1) mx = fmaxf(mx, __shfl_xor_sync(FULL, mx, o));
    if (lane == 0) s_ws[wrp] = mx;
    __syncthreads();
    if (wrp == 0) {
        float am = s_ws[lane];
        #pragma unroll
        for (int o = 16; o; o >>= 1) am = fmaxf(am, __shfl_xor_sync(FULL, am, o));
        if (lane == 0) s_M = am;
    }
    __syncthreads();
    const float M = s_M;

    // -------- Phase 4: e_i = exp(x_i - M); additive suffix-sum scan ----------
    const float e0 = __expf(x0 - M);
    const float e1 = __expf(x1 - M);
    const float e2 = __expf(x2 - M);
    const float e3 = __expf(x3 - M);

    float v = e0 + e1 + e2 + e3;              // chunk sum
    float inc = v;                            // warp inclusive suffix sum
    #pragma unroll
    for (int d = 1; d < 32; d <<= 1) {
        const float t = __shfl_down_sync(FULL, inc, d);
        if (lane + d < 32) inc += t;
    }
    if (lane == 0) s_ws[wrp] = inc;           // whole-warp sum
    __syncthreads();
    if (wrp == 0) {
        float av = s_ws[lane];
        #pragma unroll
        for (int d = 1; d < 32; d <<= 1) {
            const float t = __shfl_down_sync(FULL, av, d);
            if (lane + d < 32) av += t;
        }
        s_ws[lane] = av;                      // inclusive suffix over warps lane..31
    }
    __syncthreads();

    // Exclusive suffix carry for this thread's chunk.
    float ex = __shfl_down_sync(FULL, inc, 1);
    ex = (lane < 31) ? ex : 0.0f;
    const float Sc = ex + ((wrp < 31) ? s_ws[wrp + 1] : 0.0f);

    // -------- Phase 5: replay (descending), denom = M + log(S) ---------------
    float rs  = Sc;
    float acc = 0.0f;
    rs += e3; acc += (x3 - M) - __logf(rs);
    rs += e2; acc += (x2 - M) - __logf(rs);
    rs += e1; acc += (x1 - M) - __logf(rs);
    rs += e0; acc += (x0 - M) - __logf(rs);

    // -------- Phase 6: block reduce + completion-counter finalize ------------
    #pragma unroll
    for (int o = 16; o; o >>= 1) acc += __shfl_xor_sync(FULL, acc, o);
    if (lane == 0) s_red[wrp] = acc;
    __syncthreads();
    if (tid == 0) {
        float t = 0.0f;
        #pragma unroll
        for (int w = 0; w < 32; w++) t += s_red[w];
        atomicAdd(&g_acc, (double)t);
        __threadfence();
        const unsigned int ticket = atomicAdd(&g_done, 1u);
        if (ticket == gridDim.x - 1) {
            out[0] = (float)(-g_acc / (double)gridDim.x);
            g_acc  = 0.0;        // reset for next graph replay
            g_done = 0u;
            __threadfence();
        }
    }
}

extern "C" void kernel_launch(void* const* d_in, const int* in_sizes, int n_in,
                              void* d_out, int out_size) {
    const float* X        = (const float*)d_in[0];
    const float* W        = (const float*)d_in[1];
    const float* bias     = (const float*)d_in[2];
    const int*   rankings = (const int*)d_in[3];
    float* out = (float*)d_out;

    const int BN = in_sizes[3];   // B * N
    const int B  = BN / NN;       // N fixed at 4096

    fused_kernel<<<B, T>>>(X, W, bias, rankings, out);
}